// round 1
// baseline (speedup 1.0000x reference)
#include <cuda_runtime.h>

// ---------------------------------------------------------------------------
// TypeGAT HICS strategy, inverted formulation.
//
// Instead of per-entity scans over all E edges (reference: dense [B,E] masks),
// we build node->entity chains + an occupancy bitmap, make one pass over the
// edges testing the bitmap in shared memory, and push matched (time,edge) keys
// into per-entity candidate buffers. A final kernel does exact top-k selection
// (time desc, index asc — matching lax.top_k tie-breaking) and the masked-mean
// aggregation over query_weight rows.
// ---------------------------------------------------------------------------

#define MAX_B        4096
#define CAP          1024           // per-entity per-direction candidate cap
#define MAX_NODES    (1 << 20)
#define BM_WORDS     (MAX_NODES / 32)
#define SMEM_BM_WORDS 8192          // 32KB smem bitmap -> up to 262144 nodes
#define MAXK         32

__device__ int                g_head[MAX_NODES];
__device__ unsigned int       g_bitmap[BM_WORDS];
__device__ int                g_next[MAX_B];
__device__ int                g_cnt_inc[MAX_B];
__device__ int                g_cnt_out[MAX_B];
__device__ unsigned long long g_buf_inc[(size_t)MAX_B * CAP];
__device__ unsigned long long g_buf_out[(size_t)MAX_B * CAP];

// Orderable key: (monotone float bits << 32) | ~edge_index.
// Max key == (largest time, smallest index) — matches lax.top_k tie-break.
__device__ __forceinline__ unsigned long long pack_key(float t, unsigned int e) {
    unsigned int tb = __float_as_uint(t);
    tb = (tb & 0x80000000u) ? ~tb : (tb | 0x80000000u);
    return ((unsigned long long)tb << 32) | (unsigned long long)(~e);
}

// ---------------------------------------------------------------------------
// Kernel 1: reset head table + bitmap for [0, num_nodes)
// ---------------------------------------------------------------------------
__global__ void k_init(const int* __restrict__ nn_ptr) {
    int nn = nn_ptr[0];
    if (nn > MAX_NODES) nn = MAX_NODES;
    int nwords = (nn + 31) >> 5;
    int total = nn > nwords ? nn : nwords;
    for (int i = blockIdx.x * blockDim.x + threadIdx.x; i < total;
         i += gridDim.x * blockDim.x) {
        if (i < nn)     g_head[i]   = -1;
        if (i < nwords) g_bitmap[i] = 0u;
    }
}

// ---------------------------------------------------------------------------
// Kernel 2: build node->entity chains + occupancy bitmap; zero counters
// ---------------------------------------------------------------------------
__global__ void k_build(const int* __restrict__ ent, const int* __restrict__ nn_ptr, int B) {
    int b = blockIdx.x * blockDim.x + threadIdx.x;
    if (b >= B || b >= MAX_B) return;
    g_cnt_inc[b] = 0;
    g_cnt_out[b] = 0;
    int nn = nn_ptr[0];
    int node = ent[b];
    if (node >= 0 && node < nn && node < MAX_NODES) {
        g_next[b] = atomicExch(&g_head[node], b);
        atomicOr(&g_bitmap[node >> 5], 1u << (node & 31));
    }
}

// ---------------------------------------------------------------------------
// Kernel 3: single pass over edges. SMEM bitmap probe per edge endpoint; on
// hit, walk the (usually length-1) entity chain and push the packed key.
// ---------------------------------------------------------------------------
__global__ void k_scan(const int* __restrict__ src, const int* __restrict__ dst,
                       const float* __restrict__ times, int E,
                       const int* __restrict__ nn_ptr) {
    __shared__ unsigned int s_bm[SMEM_BM_WORDS];
    int nn = nn_ptr[0];
    if (nn > MAX_NODES) nn = MAX_NODES;
    int nwords = (nn + 31) >> 5;
    bool use_s = (nwords <= SMEM_BM_WORDS);
    if (use_s) {
        for (int i = threadIdx.x; i < nwords; i += blockDim.x)
            s_bm[i] = g_bitmap[i];
        __syncthreads();
    }
    const unsigned int* bm = use_s ? (const unsigned int*)s_bm
                                   : (const unsigned int*)g_bitmap;

    int e = blockIdx.x * blockDim.x + threadIdx.x;
    if (e >= E) return;

    int d = dst[e];
    int s = src[e];
    bool hd = (d >= 0) && (d < nn) && ((bm[d >> 5] >> (d & 31)) & 1u);
    bool hs = (s >= 0) && (s < nn) && ((bm[s >> 5] >> (s & 31)) & 1u);
    if (hd | hs) {
        unsigned long long key = pack_key(times[e], (unsigned int)e);
        if (hd) {
            for (int b = g_head[d]; b >= 0; b = g_next[b]) {
                int p = atomicAdd(&g_cnt_inc[b], 1);
                if (p < CAP) g_buf_inc[(size_t)b * CAP + p] = key;
            }
        }
        if (hs) {
            for (int b = g_head[s]; b >= 0; b = g_next[b]) {
                int p = atomicAdd(&g_cnt_out[b], 1);
                if (p < CAP) g_buf_out[(size_t)b * CAP + p] = key;
            }
        }
    }
}

// ---------------------------------------------------------------------------
// Kernel 4: per-entity exact top-k selection + masked-mean aggregation.
// One block per entity; thread 0 does the (tiny) selection, all threads
// gather & sum query_weight rows.
// ---------------------------------------------------------------------------
__global__ void k_agg(const int* __restrict__ etypes, const float* __restrict__ qw,
                      float* __restrict__ out, int B, int D,
                      const int* __restrict__ k_ptr) {
    int b = blockIdx.x;
    if (b >= B) return;

    __shared__ int s_types[2 * MAXK];
    __shared__ int s_cnt;

    if (threadIdx.x == 0) {
        int k = k_ptr[0];
        if (k > MAXK) k = MAXK;
        if (k < 0)    k = 0;
        int kh = k / 2;

        int nIncTot = g_cnt_inc[b];
        int nOutTot = g_cnt_out[b];
        int nInc = nIncTot < CAP ? nIncTot : CAP;
        int nOut = nOutTot < CAP ? nOutTot : CAP;

        int inc_take  = kh < nIncTot ? kh : nIncTot;
        int remaining = (inc_take > 0) ? (k - inc_take) : k;
        int out_take  = remaining < nOutTot ? remaining : nOutTot;

        unsigned long long top[MAXK];
        int nsel = 0;

        // ---- top inc_take incoming (maintain sorted-desc top-kh) ----
        {
            const unsigned long long* buf = &g_buf_inc[(size_t)b * CAP];
            int c = 0;
            for (int i = 0; i < nInc; ++i) {
                unsigned long long key = buf[i];
                if (c < kh) {
                    int j = c++;
                    while (j > 0 && top[j - 1] < key) { top[j] = top[j - 1]; --j; }
                    top[j] = key;
                } else if (kh > 0 && key > top[kh - 1]) {
                    int j = kh - 1;
                    while (j > 0 && top[j - 1] < key) { top[j] = top[j - 1]; --j; }
                    top[j] = key;
                }
            }
            for (int i = 0; i < inc_take; ++i) {
                unsigned int e = ~(unsigned int)(top[i] & 0xFFFFFFFFull);
                s_types[nsel++] = etypes[e];
            }
        }

        // ---- top out_take outgoing (maintain sorted-desc top-k) ----
        {
            const unsigned long long* buf = &g_buf_out[(size_t)b * CAP];
            int c = 0;
            for (int i = 0; i < nOut; ++i) {
                unsigned long long key = buf[i];
                if (c < k) {
                    int j = c++;
                    while (j > 0 && top[j - 1] < key) { top[j] = top[j - 1]; --j; }
                    top[j] = key;
                } else if (k > 0 && key > top[k - 1]) {
                    int j = k - 1;
                    while (j > 0 && top[j - 1] < key) { top[j] = top[j - 1]; --j; }
                    top[j] = key;
                }
            }
            for (int i = 0; i < out_take; ++i) {
                unsigned int e = ~(unsigned int)(top[i] & 0xFFFFFFFFull);
                s_types[nsel++] = etypes[e];
            }
        }
        s_cnt = nsel;
    }
    __syncthreads();

    int n = s_cnt;
    float denom = fmaxf((float)n, 1.0f);
    for (int d = threadIdx.x; d < D; d += blockDim.x) {
        float sum = 0.0f;
        for (int i = 0; i < n; ++i)
            sum += qw[(size_t)s_types[i] * D + d];
        out[(size_t)b * D + d] = sum / denom;
    }
}

// ---------------------------------------------------------------------------
// Host launcher (graph-capturable: launches only)
// Inputs (metadata order): entity_index, edge_src, edge_dst, edge_types,
// edge_times, query_weight, k, num_nodes.
// ---------------------------------------------------------------------------
extern "C" void kernel_launch(void* const* d_in, const int* in_sizes, int n_in,
                              void* d_out, int out_size) {
    const int*   ent = (const int*)d_in[0];
    const int*   src = (const int*)d_in[1];
    const int*   dst = (const int*)d_in[2];
    const int*   typ = (const int*)d_in[3];
    const float* tim = (const float*)d_in[4];
    const float* qw  = (const float*)d_in[5];
    const int*   kp  = (const int*)d_in[6];
    const int*   nnp = (const int*)d_in[7];

    int B = in_sizes[0];
    int E = in_sizes[1];
    int D = (B > 0) ? (out_size / B) : 0;

    k_init <<<256, 256>>>(nnp);
    k_build<<<(B + 255) / 256, 256>>>(ent, nnp, B);
    k_scan <<<(E + 255) / 256, 256>>>(src, dst, tim, E, nnp);
    k_agg  <<<B, 128>>>(typ, qw, (float*)d_out, B, D, kp);
}

// round 2
// speedup vs baseline: 1.2771x; 1.2771x over previous
#include <cuda_runtime.h>

// ---------------------------------------------------------------------------
// TypeGAT HICS, inverted formulation, v2.
//   k_setup : single block — clear only the touched head slots + bitmap +
//             counters, then build node->entity chains.
//   k_scan  : grid-stride pass over edges; SMEM bitmap probe; push packed
//             (time,edge) keys into per-entity candidate buffers.
//   k_agg   : warp-parallel exact top-k (rank-by-shfl, register-resident,
//             no spills) + masked-mean over query_weight rows.
// Key packing preserves lax.top_k ordering: time desc, edge index asc.
// ---------------------------------------------------------------------------

#define MAX_B        4096
#define CAP          1024
#define MAX_NODES    (1 << 20)
#define BM_WORDS     (MAX_NODES / 32)
#define SMEM_BM_WORDS 8192
#define MAXK         32

__device__ int                g_head[MAX_NODES];
__device__ unsigned int       g_bitmap[BM_WORDS];
__device__ int                g_next[MAX_B];
__device__ int                g_cnt_inc[MAX_B];
__device__ int                g_cnt_out[MAX_B];
__device__ unsigned long long g_buf_inc[(size_t)MAX_B * CAP];
__device__ unsigned long long g_buf_out[(size_t)MAX_B * CAP];

// Orderable key: (monotone float bits << 32) | ~edge_index.
// Max key == (largest time, smallest index) — matches lax.top_k tie-break.
// Keys of valid edges are globally distinct (distinct edge index).
__device__ __forceinline__ unsigned long long pack_key(float t, unsigned int e) {
    unsigned int tb = __float_as_uint(t);
    tb = (tb & 0x80000000u) ? ~tb : (tb | 0x80000000u);
    return ((unsigned long long)tb << 32) | (unsigned long long)(~e);
}

// ---------------------------------------------------------------------------
// Kernel 1: single-block setup. Clears only what this batch touches.
// ---------------------------------------------------------------------------
__global__ void k_setup(const int* __restrict__ ent, const int* __restrict__ nn_ptr, int B) {
    int nn = nn_ptr[0];
    if (nn > MAX_NODES) nn = MAX_NODES;
    int nwords = (nn + 31) >> 5;
    int t = threadIdx.x;

    for (int i = t; i < nwords; i += blockDim.x) g_bitmap[i] = 0u;
    for (int b = t; b < B && b < MAX_B; b += blockDim.x) {
        g_cnt_inc[b] = 0;
        g_cnt_out[b] = 0;
        int node = ent[b];
        if (node >= 0 && node < nn) g_head[node] = -1;   // benign dup races
    }
    __syncthreads();
    for (int b = t; b < B && b < MAX_B; b += blockDim.x) {
        int node = ent[b];
        if (node >= 0 && node < nn) {
            g_next[b] = atomicExch(&g_head[node], b);
            atomicOr(&g_bitmap[node >> 5], 1u << (node & 31));
        }
    }
}

// ---------------------------------------------------------------------------
// Kernel 2: grid-stride edge scan with SMEM bitmap probe.
// ---------------------------------------------------------------------------
__global__ void k_scan(const int* __restrict__ src, const int* __restrict__ dst,
                       const float* __restrict__ times, int E,
                       const int* __restrict__ nn_ptr) {
    __shared__ unsigned int s_bm[SMEM_BM_WORDS];
    int nn = nn_ptr[0];
    if (nn > MAX_NODES) nn = MAX_NODES;
    int nwords = (nn + 31) >> 5;
    bool use_s = (nwords <= SMEM_BM_WORDS);
    if (use_s) {
        for (int i = threadIdx.x; i < nwords; i += blockDim.x)
            s_bm[i] = g_bitmap[i];
        __syncthreads();
    }
    const unsigned int* bm = use_s ? (const unsigned int*)s_bm
                                   : (const unsigned int*)g_bitmap;

    int stride = gridDim.x * blockDim.x;
    for (int e = blockIdx.x * blockDim.x + threadIdx.x; e < E; e += stride) {
        int d = dst[e];
        int s = src[e];
        bool hd = (d >= 0) && (d < nn) && ((bm[d >> 5] >> (d & 31)) & 1u);
        bool hs = (s >= 0) && (s < nn) && ((bm[s >> 5] >> (s & 31)) & 1u);
        if (hd | hs) {
            unsigned long long key = pack_key(times[e], (unsigned int)e);
            if (hd) {
                for (int b = g_head[d]; b >= 0; b = g_next[b]) {
                    int p = atomicAdd(&g_cnt_inc[b], 1);
                    if (p < CAP) g_buf_inc[(size_t)b * CAP + p] = key;
                }
            }
            if (hs) {
                for (int b = g_head[s]; b >= 0; b = g_next[b]) {
                    int p = atomicAdd(&g_cnt_out[b], 1);
                    if (p < CAP) g_buf_out[(size_t)b * CAP + p] = key;
                }
            }
        }
    }
}

// ---------------------------------------------------------------------------
// Warp-parallel exact top-`take` selection; writes etypes[edge] to
// s_types[off + rank]. Register-resident, tie-free (distinct keys).
// ---------------------------------------------------------------------------
__device__ __forceinline__ void warp_select(const unsigned long long* __restrict__ buf,
                                            int n, int take,
                                            const int* __restrict__ etypes,
                                            int* s_types, int off, int lane) {
    if (take <= 0) return;
    if (n <= 32) {
        unsigned long long key = (lane < n) ? buf[lane] : 0ull;
        int rank = 0;
#pragma unroll
        for (int j = 0; j < 32; ++j) {
            unsigned long long o = __shfl_sync(0xffffffffu, key, j);
            rank += (o > key);
        }
        if (lane < n && rank < take)
            s_types[off + rank] = etypes[~(unsigned int)key];
    } else {
        // Rare: iterative warp-max with descending threshold.
        unsigned long long thresh = ~0ull;
        for (int r = 0; r < take; ++r) {
            unsigned long long best = 0ull;
            for (int i = lane; i < n; i += 32) {
                unsigned long long key = buf[i];
                if (key < thresh && key > best) best = key;
            }
#pragma unroll
            for (int o = 16; o; o >>= 1) {
                unsigned long long v = __shfl_xor_sync(0xffffffffu, best, o);
                if (v > best) best = v;
            }
            if (lane == 0) s_types[off + r] = etypes[~(unsigned int)best];
            thresh = best;
        }
    }
}

// ---------------------------------------------------------------------------
// Kernel 3: per-entity selection + masked-mean aggregation.
// Warp 0: incoming top-k/2. Warp 1: outgoing top-k. All 128: weight sum.
// ---------------------------------------------------------------------------
__global__ void k_agg(const int* __restrict__ etypes, const float* __restrict__ qw,
                      float* __restrict__ out, int B, int D,
                      const int* __restrict__ k_ptr) {
    int b = blockIdx.x;
    if (b >= B) return;

    __shared__ int s_types[3 * MAXK];
    __shared__ int s_n;

    int tid = threadIdx.x, wid = tid >> 5, lane = tid & 31;

    if (wid < 2) {
        int k = k_ptr[0];
        if (k > MAXK) k = MAXK;
        if (k < 0)    k = 0;
        int kh = k >> 1;

        int cin  = g_cnt_inc[b];
        int cout = g_cnt_out[b];
        int nInc = cin  < CAP ? cin  : CAP;
        int nOut = cout < CAP ? cout : CAP;

        int inc_take  = kh < cin ? kh : cin;
        int remaining = (inc_take > 0) ? (k - inc_take) : k;
        int out_take  = remaining < cout ? remaining : cout;

        if (wid == 0) {
            warp_select(&g_buf_inc[(size_t)b * CAP], nInc, inc_take,
                        etypes, s_types, 0, lane);
            if (lane == 0) s_n = inc_take + out_take;
        } else {
            warp_select(&g_buf_out[(size_t)b * CAP], nOut, out_take,
                        etypes, s_types, inc_take, lane);
        }
    }
    __syncthreads();

    int n = s_n;
    float denom = fmaxf((float)n, 1.0f);
    for (int d = tid; d < D; d += blockDim.x) {
        float sum = 0.0f;
        for (int i = 0; i < n; ++i)
            sum += qw[(size_t)s_types[i] * D + d];
        out[(size_t)b * D + d] = sum / denom;
    }
}

// ---------------------------------------------------------------------------
// Host launcher (graph-capturable: launches only).
// Inputs: entity_index, edge_src, edge_dst, edge_types, edge_times,
//         query_weight, k, num_nodes.
// ---------------------------------------------------------------------------
extern "C" void kernel_launch(void* const* d_in, const int* in_sizes, int n_in,
                              void* d_out, int out_size) {
    const int*   ent = (const int*)d_in[0];
    const int*   src = (const int*)d_in[1];
    const int*   dst = (const int*)d_in[2];
    const int*   typ = (const int*)d_in[3];
    const float* tim = (const float*)d_in[4];
    const float* qw  = (const float*)d_in[5];
    const int*   kp  = (const int*)d_in[6];
    const int*   nnp = (const int*)d_in[7];

    int B = in_sizes[0];
    int E = in_sizes[1];
    int D = (B > 0) ? (out_size / B) : 0;

    k_setup<<<1, 1024>>>(ent, nnp, B);
    k_scan <<<256, 256>>>(src, dst, tim, E, nnp);
    k_agg  <<<B, 128>>>(typ, qw, (float*)d_out, B, D, kp);
}

// round 3
// speedup vs baseline: 1.6091x; 1.2600x over previous
#include <cuda_runtime.h>

// ---------------------------------------------------------------------------
// TypeGAT HICS, inverted formulation, v3 — two kernels.
//
//  k_scan : each block builds a private SMEM hash (node -> entity) from
//           entity_index, then grid-strides the edges with int4 loads.
//           Hits push packed (time,edge) keys into per-entity buffers.
//  k_agg  : warp-parallel exact top-k (rank-by-shfl) + masked mean over
//           query_weight rows. Resets the per-entity counters to zero on
//           exit, restoring the module-load invariant for the next call.
//
// Key packing preserves lax.top_k ordering: time desc, edge index asc.
// ---------------------------------------------------------------------------

#define MAX_B       4096
#define CAP         1024
#define MAX_NODES   (1 << 20)
#define MAXK        32
#define HASH_SLOTS  4096
#define HASH_MASK   (HASH_SLOTS - 1)
#define EMPTY       0xFFFFFFFFu

__device__ int                g_cnt_inc[MAX_B];   // zero at module load;
__device__ int                g_cnt_out[MAX_B];   // k_agg restores zero.
__device__ unsigned long long g_buf_inc[(size_t)MAX_B * CAP];
__device__ unsigned long long g_buf_out[(size_t)MAX_B * CAP];

__device__ __forceinline__ unsigned int hash_node(unsigned int node) {
    return (node * 2654435761u) >> 20;   // top 12 bits -> [0, 4096)
}

// Orderable key: (monotone float bits << 32) | ~edge_index.
// Max key == (largest time, smallest index) — matches lax.top_k tie-break.
__device__ __forceinline__ unsigned long long pack_key(float t, unsigned int e) {
    unsigned int tb = __float_as_uint(t);
    tb = (tb & 0x80000000u) ? ~tb : (tb | 0x80000000u);
    return ((unsigned long long)tb << 32) | (unsigned long long)(~e);
}

__device__ __forceinline__ bool probe_any(const unsigned int* s_tab, unsigned int node) {
    if (node >= (unsigned int)MAX_NODES) return false;
    unsigned int h = hash_node(node), v;
    while ((v = s_tab[h]) != EMPTY) {
        if ((v >> 12) == node) return true;
        h = (h + 1) & HASH_MASK;
    }
    return false;
}

__device__ __forceinline__ void probe_push(const unsigned int* s_tab, unsigned int node,
                                           unsigned long long key,
                                           int* __restrict__ cnt,
                                           unsigned long long* __restrict__ buf) {
    unsigned int h = hash_node(node), v;
    while ((v = s_tab[h]) != EMPTY) {
        if ((v >> 12) == node) {
            int b = (int)(v & 0xFFFu);
            int p = atomicAdd(&cnt[b], 1);
            if (p < CAP) buf[(size_t)b * CAP + p] = key;
        }
        h = (h + 1) & HASH_MASK;
    }
}

// ---------------------------------------------------------------------------
// Kernel 1: edge scan with per-block SMEM hash.
// ---------------------------------------------------------------------------
__global__ void k_scan(const int* __restrict__ src, const int* __restrict__ dst,
                       const float* __restrict__ times, int E,
                       const int* __restrict__ ent, int B,
                       const int* __restrict__ nn_ptr) {
    __shared__ unsigned int s_tab[HASH_SLOTS];
    for (int i = threadIdx.x; i < HASH_SLOTS; i += blockDim.x) s_tab[i] = EMPTY;
    __syncthreads();

    int nn = nn_ptr[0];
    if (nn > MAX_NODES) nn = MAX_NODES;
    for (int b = threadIdx.x; b < B && b < MAX_B; b += blockDim.x) {
        int node = ent[b];
        if (node >= 0 && node < nn) {
            unsigned int val = ((unsigned int)node << 12) | (unsigned int)b;
            unsigned int h = hash_node((unsigned int)node);
            while (atomicCAS(&s_tab[h], EMPTY, val) != EMPTY) h = (h + 1) & HASH_MASK;
        }
    }
    __syncthreads();

    int tid    = blockIdx.x * blockDim.x + threadIdx.x;
    int stride = gridDim.x * blockDim.x;
    int E4     = E >> 2;
    const int4* src4 = (const int4*)src;
    const int4* dst4 = (const int4*)dst;

    for (int i = tid; i < E4; i += stride) {
        int4 d4 = dst4[i];
        int4 s4 = src4[i];
        int e0 = i << 2;
#pragma unroll
        for (int j = 0; j < 4; ++j) {
            unsigned int d = (unsigned int)((j == 0) ? d4.x : (j == 1) ? d4.y : (j == 2) ? d4.z : d4.w);
            unsigned int s = (unsigned int)((j == 0) ? s4.x : (j == 1) ? s4.y : (j == 2) ? s4.z : s4.w);
            bool hd = probe_any(s_tab, d);
            bool hs = probe_any(s_tab, s);
            if (hd | hs) {
                int e = e0 + j;
                unsigned long long key = pack_key(times[e], (unsigned int)e);
                if (hd) probe_push(s_tab, d, key, g_cnt_inc, g_buf_inc);
                if (hs) probe_push(s_tab, s, key, g_cnt_out, g_buf_out);
            }
        }
    }
    // tail (E not multiple of 4)
    for (int e = (E4 << 2) + tid; e < E; e += stride) {
        unsigned int d = (unsigned int)dst[e];
        unsigned int s = (unsigned int)src[e];
        bool hd = probe_any(s_tab, d);
        bool hs = probe_any(s_tab, s);
        if (hd | hs) {
            unsigned long long key = pack_key(times[e], (unsigned int)e);
            if (hd) probe_push(s_tab, d, key, g_cnt_inc, g_buf_inc);
            if (hs) probe_push(s_tab, s, key, g_cnt_out, g_buf_out);
        }
    }
}

// ---------------------------------------------------------------------------
// Warp-parallel exact top-`take` selection; writes etypes[edge] into
// s_types[off + rank]. Tie-free (distinct packed keys).
// ---------------------------------------------------------------------------
__device__ __forceinline__ void warp_select(const unsigned long long* __restrict__ buf,
                                            int n, int take,
                                            const int* __restrict__ etypes,
                                            int* s_types, int off, int lane) {
    if (take <= 0) return;
    if (n <= 32) {
        unsigned long long key = (lane < n) ? buf[lane] : 0ull;
        int rank = 0;
#pragma unroll
        for (int j = 0; j < 32; ++j) {
            unsigned long long o = __shfl_sync(0xffffffffu, key, j);
            rank += (o > key);
        }
        if (lane < n && rank < take)
            s_types[off + rank] = etypes[~(unsigned int)key];
    } else {
        unsigned long long thresh = ~0ull;
        for (int r = 0; r < take; ++r) {
            unsigned long long best = 0ull;
            for (int i = lane; i < n; i += 32) {
                unsigned long long key = buf[i];
                if (key < thresh && key > best) best = key;
            }
#pragma unroll
            for (int o = 16; o; o >>= 1) {
                unsigned long long v = __shfl_xor_sync(0xffffffffu, best, o);
                if (v > best) best = v;
            }
            if (lane == 0) s_types[off + r] = etypes[~(unsigned int)best];
            thresh = best;
        }
    }
}

// ---------------------------------------------------------------------------
// Kernel 2: per-entity selection + masked-mean; restores counters to zero.
// ---------------------------------------------------------------------------
__global__ void k_agg(const int* __restrict__ etypes, const float* __restrict__ qw,
                      float* __restrict__ out, int B, int D,
                      const int* __restrict__ k_ptr) {
    int b = blockIdx.x;
    if (b >= B) return;

    __shared__ int s_types[3 * MAXK];
    __shared__ int s_n;

    int tid = threadIdx.x, wid = tid >> 5, lane = tid & 31;

    if (wid < 2) {
        int k = k_ptr[0];
        if (k > MAXK) k = MAXK;
        if (k < 0)    k = 0;
        int kh = k >> 1;

        int cin  = g_cnt_inc[b];
        int cout = g_cnt_out[b];
        int nInc = cin  < CAP ? cin  : CAP;
        int nOut = cout < CAP ? cout : CAP;

        int inc_take  = kh < cin ? kh : cin;
        int remaining = (inc_take > 0) ? (k - inc_take) : k;
        int out_take  = remaining < cout ? remaining : cout;

        if (wid == 0) {
            warp_select(&g_buf_inc[(size_t)b * CAP], nInc, inc_take,
                        etypes, s_types, 0, lane);
            if (lane == 0) s_n = inc_take + out_take;
        } else {
            warp_select(&g_buf_out[(size_t)b * CAP], nOut, out_take,
                        etypes, s_types, inc_take, lane);
        }
    }
    __syncthreads();

    int n = s_n;
    float denom = fmaxf((float)n, 1.0f);
    for (int d = tid; d < D; d += blockDim.x) {
        float sum = 0.0f;
        for (int i = 0; i < n; ++i)
            sum += qw[(size_t)s_types[i] * D + d];
        out[(size_t)b * D + d] = sum / denom;
    }

    // Restore module-load invariant (counters zero) for the next invocation.
    if (tid == 0) {
        g_cnt_inc[b] = 0;
        g_cnt_out[b] = 0;
    }
}

// ---------------------------------------------------------------------------
// Host launcher (graph-capturable: launches only).
// Inputs: entity_index, edge_src, edge_dst, edge_types, edge_times,
//         query_weight, k, num_nodes.
// ---------------------------------------------------------------------------
extern "C" void kernel_launch(void* const* d_in, const int* in_sizes, int n_in,
                              void* d_out, int out_size) {
    const int*   ent = (const int*)d_in[0];
    const int*   src = (const int*)d_in[1];
    const int*   dst = (const int*)d_in[2];
    const int*   typ = (const int*)d_in[3];
    const float* tim = (const float*)d_in[4];
    const float* qw  = (const float*)d_in[5];
    const int*   kp  = (const int*)d_in[6];
    const int*   nnp = (const int*)d_in[7];

    int B = in_sizes[0];
    int E = in_sizes[1];
    int D = (B > 0) ? (out_size / B) : 0;

    int nblk = (E / 4 + 255) / 256;
    if (nblk > 256) nblk = 256;
    if (nblk < 1)   nblk = 1;

    k_scan<<<nblk, 256>>>(src, dst, tim, E, ent, B, nnp);
    k_agg <<<B, 128>>>(typ, qw, (float*)d_out, B, D, kp);
}